// round 10
// baseline (speedup 1.0000x reference)
#include <cuda_runtime.h>
#include <cuda_bf16.h>
#include <mma.h>
#include <cstdint>

using namespace nvcuda;

#define CDIM 128
#define HW   65536
#define NP   128                 // pixels per tile
#define NT   (4 * (HW / NP))     // 2048 tiles
#define GRID 148
#define LDW  136                 // padded bf16 row stride (mult of 8)

__device__ float          g_bias[CDIM];
__device__ unsigned short g_Whi[CDIM*CDIM];   // bf16 bits, [o][c]
__device__ unsigned short g_Wlo[CDIM*CDIM];
__device__ float g_T1[CDIM*CDIM];
__device__ float g_T2[CDIM*CDIM];

// ---------------------------------------------------------------------------
// Setup 1: T1 = amp_w @ G_re, T2 = phase_w @ G_im (algebra verified in R2)
// ---------------------------------------------------------------------------
__global__ void setup1_kernel(const float* __restrict__ amp_w,
                              const float* __restrict__ phase_w,
                              const float* __restrict__ freq_mask) {
    int o = blockIdx.x, k = threadIdx.x;
    __shared__ float AM[CDIM], PM[CDIM], CT[CDIM], ST[CDIM];
    float m = freq_mask[k];
    AM[k] = amp_w[o*CDIM + k] * m;
    PM[k] = phase_w[o*CDIM + k] * m;
    float s, c;
    sincospif(2.0f * (float)k / (float)CDIM, &s, &c);
    CT[k] = c; ST[k] = s;
    __syncthreads();
    float t1 = 0.f, t2 = 0.f;
    #pragma unroll 8
    for (int cc = 0; cc < CDIM; cc++) {
        int idx = (cc * k) & (CDIM - 1);
        t1 += AM[cc] * CT[idx];
        t2 -= PM[cc] * ST[idx];
    }
    float sgnk = (k & 1) ? -1.f : 1.f;
    g_T1[o*CDIM + k] = t1 * sgnk;
    g_T2[o*CDIM + k] = t2 * sgnk;
}

// ---------------------------------------------------------------------------
// Setup 2: W[n][k] = ((-1)^n/128) * sum_j [cos*T1 - sin*T2]; bf16 hi/lo split.
// ---------------------------------------------------------------------------
__global__ void setup2_kernel(const float* __restrict__ amp_b,
                              const float* __restrict__ phase_b) {
    int n = blockIdx.x, k = threadIdx.x;
    __shared__ float CT[CDIM], ST[CDIM];
    float s, c;
    sincospif(2.0f * (float)k / (float)CDIM, &s, &c);
    CT[k] = c; ST[k] = s;
    __syncthreads();
    float acc = 0.f;
    #pragma unroll 8
    for (int j = 0; j < CDIM; j++) {
        int idx = (n * j) & (CDIM - 1);
        acc += CT[idx] * g_T1[j*CDIM + k] - ST[idx] * g_T2[j*CDIM + k];
    }
    float sc = ((n & 1) ? -1.f : 1.f) / (float)CDIM;
    float w = acc * sc;                               // W[n][k]
    __nv_bfloat16 hi = __float2bfloat16(w);
    __nv_bfloat16 lo = __float2bfloat16(w - __bfloat162float(hi));
    g_Whi[n*CDIM + k] = __bfloat16_as_ushort(hi);
    g_Wlo[n*CDIM + k] = __bfloat16_as_ushort(lo);
    if (k == 0) {
        float bb = 0.f;
        for (int j = 0; j < CDIM; j++) {
            int idx = (n * j) & (CDIM - 1);
            bb += CT[idx] * amp_b[j] - ST[idx] * phase_b[j];
        }
        g_bias[n] = bb * sc;
    }
}

// ---------------------------------------------------------------------------
// Helpers
// ---------------------------------------------------------------------------
__device__ __forceinline__ uint32_t cvt_bf16x2(float hi, float lo) {
    uint32_t r;
    asm("cvt.rn.bf16x2.f32 %0, %1, %2;" : "=r"(r) : "f"(hi), "f"(lo));
    return r;
}
__device__ __forceinline__ void bar_sync(int id, int cnt) {
    asm volatile("bar.sync %0, %1;" :: "r"(id), "r"(cnt) : "memory");
}
__device__ __forceinline__ void bar_arrive(int id, int cnt) {
    asm volatile("bar.arrive %0, %1;" :: "r"(id), "r"(cnt) : "memory");
}

// smem layout (bytes)
#define OFF_WH   0
#define OFF_WL   34816
#define OFF_X0   69632                  // Xh0 (34816) + Xl0 (34816)
#define OFF_X1   139264                 // Xh1 + Xl1
#define OFF_BIAS 208896
#define SM_TOTAL 217088

#define NTHREADS 384                    // 8 consumer warps + 4 producer warps
#define BAR_FULL0  1
#define BAR_FULL1  2
#define BAR_EMPTY0 3
#define BAR_EMPTY1 4

// ---------------------------------------------------------------------------
// Warp-specialized GEMM: consumer warps (0-7) run MMA+epilogue back-to-back;
// producer warps (8-11) LDG f32 -> bf16 hi/lo -> STS into double-buffered
// Xh/Xl. Named-barrier handshake (count=384: 256 sync + 128 arrive or
// 128 sync + 256 arrive). Convert phase vanishes from the critical path.
// Out[b,o,p] = relu( sum_c W[o,c]*X[b,c,p] + bias[o] ), 3-product bf16 split.
// ---------------------------------------------------------------------------
__global__ __launch_bounds__(NTHREADS, 1)
void gemm_wmma_kernel(const float* __restrict__ X, float* __restrict__ Out) {
    extern __shared__ char smraw[];
    __nv_bfloat16* Wh = (__nv_bfloat16*)(smraw + OFF_WH);
    __nv_bfloat16* Wl = (__nv_bfloat16*)(smraw + OFF_WL);
    float*      biasM = (float*)(smraw + OFF_BIAS);   // [128][16]

    int tid = threadIdx.x;
    int wid = tid >> 5;

    // one-time: W hi/lo + bias matrix into smem (all 384 threads)
    for (int i = tid; i < CDIM*CDIM; i += NTHREADS) {
        int o = i >> 7, c = i & 127;
        Wh[o*LDW + c] = __ushort_as_bfloat16(g_Whi[i]);
        Wl[o*LDW + c] = __ushort_as_bfloat16(g_Wlo[i]);
    }
    for (int i = tid; i < CDIM*16; i += NTHREADS)
        biasM[i] = g_bias[i >> 4];
    __syncthreads();

    if (wid >= 8) {
        // ================= PRODUCER (warps 8-11, 128 threads) ================
        int ptid = tid - 256;    // 0..127
        int it = 0;
        for (int t = blockIdx.x; t < NT; t += GRID, ++it) {
            int buf = it & 1;
            __nv_bfloat16* Xh = (__nv_bfloat16*)(smraw + (buf ? OFF_X1 : OFF_X0));
            __nv_bfloat16* Xl = Xh + CDIM*LDW;
            if (it >= 2) bar_sync(buf ? BAR_EMPTY1 : BAR_EMPTY0, NTHREADS);

            int b = t >> 9, p0 = (t & 511) * NP;
            const float* Xb = X + ((size_t)b * CDIM) * HW + p0;
            #pragma unroll
            for (int itr = 0; itr < 32; itr++) {
                int i = ptid + itr*128;        // 0..4095
                int row = i >> 5, c4 = i & 31;
                float4 v = *(const float4*)(Xb + (size_t)row * HW + c4*4);
                uint32_t h0 = cvt_bf16x2(v.y, v.x);
                uint32_t h1 = cvt_bf16x2(v.w, v.z);
                float f0 = __uint_as_float(h0 << 16);
                float f1 = __uint_as_float(h0 & 0xffff0000u);
                float f2 = __uint_as_float(h1 << 16);
                float f3 = __uint_as_float(h1 & 0xffff0000u);
                uint32_t l0 = cvt_bf16x2(v.y - f1, v.x - f0);
                uint32_t l1 = cvt_bf16x2(v.w - f3, v.z - f2);
                *(uint2*)(Xh + row*LDW + c4*4) = make_uint2(h0, h1);
                *(uint2*)(Xl + row*LDW + c4*4) = make_uint2(l0, l1);
            }
            bar_arrive(buf ? BAR_FULL1 : BAR_FULL0, NTHREADS);
        }
    } else {
        // ================= CONSUMER (warps 0-7, 256 threads) =================
        int wm = (wid & 3) * 32;    // o base of warp
        int wn = (wid >> 2) * 64;   // p base of warp
        int it = 0;
        for (int t = blockIdx.x; t < NT; t += GRID, ++it) {
            int buf = it & 1;
            const __nv_bfloat16* Xh = (const __nv_bfloat16*)(smraw + (buf ? OFF_X1 : OFF_X0));
            const __nv_bfloat16* Xl = Xh + CDIM*LDW;
            bar_sync(buf ? BAR_FULL1 : BAR_FULL0, NTHREADS);

            int b = t >> 9, p0 = (t & 511) * NP;

            wmma::fragment<wmma::accumulator, 16, 16, 16, float> acc[2][4];
            #pragma unroll
            for (int mi = 0; mi < 2; mi++) {
                wmma::fragment<wmma::accumulator, 16, 16, 16, float> binit;
                wmma::load_matrix_sync(binit, biasM + (wm + mi*16)*16, 16, wmma::mem_row_major);
                #pragma unroll
                for (int ni = 0; ni < 4; ni++) acc[mi][ni] = binit;
            }
            #pragma unroll
            for (int k = 0; k < CDIM; k += 16) {
                wmma::fragment<wmma::matrix_a, 16, 16, 16, __nv_bfloat16, wmma::row_major> ah[2], al[2];
                wmma::load_matrix_sync(ah[0], Wh + (wm     )*LDW + k, LDW);
                wmma::load_matrix_sync(ah[1], Wh + (wm + 16)*LDW + k, LDW);
                wmma::load_matrix_sync(al[0], Wl + (wm     )*LDW + k, LDW);
                wmma::load_matrix_sync(al[1], Wl + (wm + 16)*LDW + k, LDW);
                #pragma unroll
                for (int ni = 0; ni < 4; ni++) {
                    wmma::fragment<wmma::matrix_b, 16, 16, 16, __nv_bfloat16, wmma::row_major> bf;
                    wmma::load_matrix_sync(bf, Xh + (size_t)k*LDW + wn + ni*16, LDW);
                    #pragma unroll
                    for (int mi = 0; mi < 2; mi++) {
                        wmma::mma_sync(acc[mi][ni], ah[mi], bf, acc[mi][ni]);
                        wmma::mma_sync(acc[mi][ni], al[mi], bf, acc[mi][ni]);
                    }
                }
                #pragma unroll
                for (int ni = 0; ni < 4; ni++) {
                    wmma::fragment<wmma::matrix_b, 16, 16, 16, __nv_bfloat16, wmma::row_major> bf;
                    wmma::load_matrix_sync(bf, Xl + (size_t)k*LDW + wn + ni*16, LDW);
                    #pragma unroll
                    for (int mi = 0; mi < 2; mi++)
                        wmma::mma_sync(acc[mi][ni], ah[mi], bf, acc[mi][ni]);
                }
            }
            bar_arrive(buf ? BAR_EMPTY1 : BAR_EMPTY0, NTHREADS);

            // epilogue: relu + store (after releasing the buffer)
            #pragma unroll
            for (int mi = 0; mi < 2; mi++) {
                #pragma unroll
                for (int ni = 0; ni < 4; ni++) {
                    #pragma unroll
                    for (int e = 0; e < acc[mi][ni].num_elements; e++)
                        acc[mi][ni].x[e] = fmaxf(acc[mi][ni].x[e], 0.f);
                    float* Op = Out + ((size_t)(b*CDIM) + wm + mi*16) * HW + p0 + wn + ni*16;
                    wmma::store_matrix_sync(Op, acc[mi][ni], HW, wmma::mem_row_major);
                }
            }
        }
    }
}

// ---------------------------------------------------------------------------
extern "C" void kernel_launch(void* const* d_in, const int* in_sizes, int n_in,
                              void* d_out, int out_size) {
    const float* x       = (const float*)d_in[0];
    const float* mask    = (const float*)d_in[1];
    const float* amp_w   = (const float*)d_in[2];
    const float* amp_b   = (const float*)d_in[3];
    const float* phase_w = (const float*)d_in[4];
    const float* phase_b = (const float*)d_in[5];
    float* out = (float*)d_out;

    setup1_kernel<<<CDIM, CDIM>>>(amp_w, phase_w, mask);
    setup2_kernel<<<CDIM, CDIM>>>(amp_b, phase_b);

    cudaFuncSetAttribute(gemm_wmma_kernel,
                         cudaFuncAttributeMaxDynamicSharedMemorySize, SM_TOTAL);
    gemm_wmma_kernel<<<GRID, NTHREADS, SM_TOTAL>>>(x, out);
}